// round 1
// baseline (speedup 1.0000x reference)
#include <cuda_runtime.h>
#include <cstdint>

#define NT   256
#define BP   128
#define STR  130            // padded SMEM row stride in words (keeps 8B alignment, kills bank conflicts)
#define OMEGA 30.0f

typedef unsigned long long ull;

// ---------------- f32x2 packed-FMA helpers (sm_100+) ----------------
__device__ __forceinline__ ull fma2(ull a, ull b, ull c) {
    ull d;
    asm("fma.rn.f32x2 %0, %1, %2, %3;" : "=l"(d) : "l"(a), "l"(b), "l"(c));
    return d;
}
__device__ __forceinline__ ull dup2(float x) {
    ull d; unsigned u = __float_as_uint(x);
    asm("mov.b64 %0, {%1, %1};" : "=l"(d) : "r"(u));
    return d;
}
__device__ __forceinline__ ull pack2(float a, float b) {
    ull d;
    asm("mov.b64 %0, {%1, %2};" : "=l"(d) : "r"(__float_as_uint(a)), "r"(__float_as_uint(b)));
    return d;
}
__device__ __forceinline__ float lo2(ull a) { return __uint_as_float((unsigned)a); }
__device__ __forceinline__ float hi2(ull a) { return __uint_as_float((unsigned)(a >> 32)); }

// ---------------- accurate sin/cos, immune to --use_fast_math ----------------
// Range reduction by pi: x = n*pi + r, |r| <= pi/2 (+eps). Valid for |x| <= ~3000.
// PI_A (12 bits) and PI_B (10 bits) make n*PI_A, n*PI_B exact for n <= 2^10.
__device__ __forceinline__ float sin_poly(float r) {
    float r2 = r * r;
    float p = -2.50521084e-8f;              // -1/11!
    p = fmaf(p, r2,  2.75573192e-6f);       //  1/9!
    p = fmaf(p, r2, -1.98412698e-4f);       // -1/7!
    p = fmaf(p, r2,  8.33333333e-3f);       //  1/5!
    p = fmaf(p, r2, -1.66666667e-1f);       // -1/3!
    return fmaf(p * r2, r, r);
}
__device__ __forceinline__ float cos_poly(float r) {
    float r2 = r * r;
    float p =  2.08767570e-9f;              //  1/12!
    p = fmaf(p, r2, -2.75573192e-7f);       // -1/10!
    p = fmaf(p, r2,  2.48015873e-5f);       //  1/8!
    p = fmaf(p, r2, -1.38888889e-3f);       // -1/6!
    p = fmaf(p, r2,  4.16666667e-2f);       //  1/4!
    p = fmaf(p, r2, -0.5f);
    return fmaf(p, r2, 1.0f);
}
__device__ __forceinline__ float reduce_pi(float x, int* par) {
    float n = rintf(x * 0.318309886183790672f);   // 1/pi
    float r = fmaf(n, -3.140625f,                x);   // exact product (12-bit)
    r       = fmaf(n, -9.670257568359375e-4f,    r);   // exact product (10-bit)
    r       = fmaf(n, -6.27832957e-7f,           r);   // residual
    *par = ((int)n) & 1;
    return r;
}
__device__ __forceinline__ float sin_acc1(float x) {
    int par; float r = reduce_pi(x, &par);
    float s = sin_poly(r);
    return par ? -s : s;
}
__device__ __forceinline__ void sincos_acc(float x, float* so, float* co) {
    int par; float r = reduce_pi(x, &par);
    float s = sin_poly(r), c = cos_poly(r);
    if (par) { s = -s; c = -c; }
    *so = s; *co = c;
}

// ---------------- layer weight staging ----------------
__device__ __forceinline__ void stage(const float* __restrict__ Wg, const float* __restrict__ bg,
                                      int wcnt, int bcnt, float* sW, float* sBias, int tid) {
    for (int i = tid; i < wcnt; i += NT) sW[i] = Wg[i];
    for (int i = tid; i < bcnt; i += NT) sBias[i] = bg[i];
}

// ---------------- 128-wide sine layer: out[j][p] = sin(30*(sum_k in[k][p]*W[k][j] + b[j])) ----------------
// thread tile: 8 j x 8 p (4 f32x2 point-pairs). sInB pre-offset to feature row 0.
template <int K>
__device__ __forceinline__ void big_layer(const float* __restrict__ sInB, float* __restrict__ sOut,
                                          const float* __restrict__ sW, const float* __restrict__ sBias,
                                          int jg, int pg) {
    const float* ip  = sInB + (pg << 3);
    const float* wpb = sW + (jg << 3);
    ull acc[32];
#pragma unroll
    for (int i = 0; i < 32; i++) acc[i] = 0ull;

#pragma unroll 4
    for (int k = 0; k < K; k++) {
        const float* a = ip + k * STR;
        ull ap[4];
        ap[0] = *(const ull*)(a);
        ap[1] = *(const ull*)(a + 2);
        ap[2] = *(const ull*)(a + 4);
        ap[3] = *(const ull*)(a + 6);
        float4 wA = *(const float4*)(wpb + (k << 7));
        float4 wB = *(const float4*)(wpb + (k << 7) + 4);
        ull wq[8];
        wq[0] = dup2(wA.x); wq[1] = dup2(wA.y); wq[2] = dup2(wA.z); wq[3] = dup2(wA.w);
        wq[4] = dup2(wB.x); wq[5] = dup2(wB.y); wq[6] = dup2(wB.z); wq[7] = dup2(wB.w);
#pragma unroll
        for (int jj = 0; jj < 8; jj++)
#pragma unroll
            for (int pp = 0; pp < 4; pp++)
                acc[jj * 4 + pp] = fma2(ap[pp], wq[jj], acc[jj * 4 + pp]);
    }
    __syncthreads();   // all reads of sIn/sW done before anyone overwrites sOut (may alias sIn)

    const int j0 = jg << 3, p0 = pg << 3;
#pragma unroll
    for (int jj = 0; jj < 8; jj++) {
        float bj = sBias[j0 + jj];
        float* orow = sOut + (j0 + jj) * STR + p0;
#pragma unroll
        for (int pp = 0; pp < 4; pp++) {
            float v0 = sin_acc1(OMEGA * (lo2(acc[jj * 4 + pp]) + bj));
            float v1 = sin_acc1(OMEGA * (hi2(acc[jj * 4 + pp]) + bj));
            *(ull*)(orow + 2 * pp) = pack2(v0, v1);
        }
    }
    __syncthreads();   // epilogue (incl. sBias reads) done before next layer re-stages sW/sBias
}

// SMEM floats: sAct 128*STR | sE 78*STR | sW 128*128 | sBias 128
#define SMEM_WORDS ((128 + 78) * STR + 128 * 128 + 128)

__global__ void __launch_bounds__(NT, 1)
siren_kernel(const float* __restrict__ pts,
             const float* __restrict__ W0, const float* __restrict__ b0,
             const float* __restrict__ W1, const float* __restrict__ b1,
             const float* __restrict__ W2, const float* __restrict__ b2,
             const float* __restrict__ W3, const float* __restrict__ b3,
             const float* __restrict__ W4, const float* __restrict__ b4,
             const float* __restrict__ W5, const float* __restrict__ b5,
             const float* __restrict__ W6, const float* __restrict__ b6,
             const float* __restrict__ W7, const float* __restrict__ b7,
             float* __restrict__ out, int n) {
    extern __shared__ float sm[];
    float* sAct  = sm;                    // [128][STR]
    float* sE    = sAct + 128 * STR;      // [78][STR]: rows 0..14 scalar, 15..17 x, 18..77 trig enc
    float* sW    = sE + 78 * STR;         // up to 128x128
    float* sBias = sW + 128 * 128;        // 128

    const int tid = threadIdx.x;
    const int pbase = blockIdx.x * BP;
    const int jg = tid & 15, pg = tid >> 4;

    // ---------------- positional encoding ----------------
    for (int idx = tid; idx < BP * 3; idx += NT) {
        int p = idx / 3, c = idx - 3 * p;
        sE[(15 + c) * STR + p] = pts[pbase * 3 + idx];
    }
    __syncthreads();
    for (int t = tid; t < BP * 30; t += NT) {
        int p = t & (BP - 1);
        int i = t >> 7;                 // 0..29
        int f = i / 3, c = i - 3 * f;
        float freq = 3.14159265358979323846f * (float)(1 << f);   // fl32(pi)*2^f, matches JAX fp32
        float ang = sE[(15 + c) * STR + p] * freq;
        float s, co; sincos_acc(ang, &s, &co);
        sE[(18 + 6 * f + c) * STR + p] = s;
        sE[(21 + 6 * f + c) * STR + p] = co;
    }
    // (no sync needed here; the stage+sync below orders these writes)

    // ---------------- L0: enc(63) -> 128 ----------------
    stage(W0, b0, 63 * 128, 128, sW, sBias, tid);
    __syncthreads();
    big_layer<63>(sE + 15 * STR, sAct, sW, sBias, jg, pg);

    // ---------------- L1..L3: 128 -> 128 ----------------
    stage(W1, b1, 128 * 128, 128, sW, sBias, tid);
    __syncthreads();
    big_layer<128>(sAct, sAct, sW, sBias, jg, pg);

    stage(W2, b2, 128 * 128, 128, sW, sBias, tid);
    __syncthreads();
    big_layer<128>(sAct, sAct, sW, sBias, jg, pg);

    stage(W3, b3, 128 * 128, 128, sW, sBias, tid);
    __syncthreads();
    big_layer<128>(sAct, sAct, sW, sBias, jg, pg);

    // ---------------- L4: 128 -> 16, no activation; row0 -> density, rows1..15 -> scalar ----------------
    stage(W4, b4, 128 * 16, 16, sW, sBias, tid);
    __syncthreads();
    {
        const int j = tid & 15, pq = tid >> 4;
        const float* ip = sAct + (pq << 3);
        ull a4[4] = {0ull, 0ull, 0ull, 0ull};
#pragma unroll 4
        for (int k = 0; k < 128; k++) {
            const float* a = ip + k * STR;
            ull x0 = *(const ull*)(a);
            ull x1 = *(const ull*)(a + 2);
            ull x2 = *(const ull*)(a + 4);
            ull x3 = *(const ull*)(a + 6);
            ull w = dup2(sW[(k << 4) + j]);
            a4[0] = fma2(x0, w, a4[0]);
            a4[1] = fma2(x1, w, a4[1]);
            a4[2] = fma2(x2, w, a4[2]);
            a4[3] = fma2(x3, w, a4[3]);
        }
        float bj = sBias[j];
        if (j == 0) {
            float* od = out + n + pbase + (pq << 3);   // density block
#pragma unroll
            for (int q = 0; q < 4; q++) {
                od[2 * q]     = fmaxf(lo2(a4[q]) + bj, 0.0f);
                od[2 * q + 1] = fmaxf(hi2(a4[q]) + bj, 0.0f);
            }
        } else {
            float* orow = sE + (j - 1) * STR + (pq << 3);   // scalar features, rows 0..14
#pragma unroll
            for (int q = 0; q < 4; q++)
                *(ull*)(orow + 2 * q) = pack2(lo2(a4[q]) + bj, hi2(a4[q]) + bj);
        }
        __syncthreads();
    }

    // ---------------- L5: [scalar(15) | enc(63)] = 78 -> 128 ----------------
    stage(W5, b5, 78 * 128, 128, sW, sBias, tid);
    __syncthreads();
    big_layer<78>(sE, sAct, sW, sBias, jg, pg);

    // ---------------- L6: 128 -> 128 ----------------
    stage(W6, b6, 128 * 128, 128, sW, sBias, tid);
    __syncthreads();
    big_layer<128>(sAct, sAct, sW, sBias, jg, pg);

    // ---------------- L7: 128 -> 1 ----------------
    for (int i = tid; i < 128; i += NT) sW[i] = W7[i];
    __syncthreads();
    if (tid < BP) {
        float acc = 0.0f;
#pragma unroll 8
        for (int k = 0; k < 128; k++)
            acc = fmaf(sAct[k * STR + tid], sW[k], acc);
        out[pbase + tid] = acc + b7[0];
    }
}

extern "C" void kernel_launch(void* const* d_in, const int* in_sizes, int n_in,
                              void* d_out, int out_size) {
    (void)n_in; (void)out_size;
    const float* pts = (const float*)d_in[0];
    const float* W0 = (const float*)d_in[1];  const float* b0 = (const float*)d_in[2];
    const float* W1 = (const float*)d_in[3];  const float* b1 = (const float*)d_in[4];
    const float* W2 = (const float*)d_in[5];  const float* b2 = (const float*)d_in[6];
    const float* W3 = (const float*)d_in[7];  const float* b3 = (const float*)d_in[8];
    const float* W4 = (const float*)d_in[9];  const float* b4 = (const float*)d_in[10];
    const float* W5 = (const float*)d_in[11]; const float* b5 = (const float*)d_in[12];
    const float* W6 = (const float*)d_in[13]; const float* b6 = (const float*)d_in[14];
    const float* W7 = (const float*)d_in[15]; const float* b7 = (const float*)d_in[16];
    float* out = (float*)d_out;

    int n = in_sizes[0] / 3;
    int blocks = n / BP;
    size_t shmem = (size_t)SMEM_WORDS * sizeof(float);   // ~173 KB

    cudaFuncSetAttribute(siren_kernel, cudaFuncAttributeMaxDynamicSharedMemorySize, (int)shmem);
    siren_kernel<<<blocks, NT, shmem>>>(pts, W0, b0, W1, b1, W2, b2, W3, b3,
                                        W4, b4, W5, b5, W6, b6, W7, b7, out, n);
}

// round 2
// speedup vs baseline: 1.4245x; 1.4245x over previous
#include <cuda_runtime.h>
#include <cstdint>

#define NT   256
#define BP   128
#define STR  130            // padded SMEM row stride in words (8B-aligned, conflict-free)
#define OMEGA 30.0f

typedef unsigned long long ull;

// ---------------- f32x2 packed-FMA helpers (sm_100+) ----------------
__device__ __forceinline__ ull fma2(ull a, ull b, ull c) {
    ull d;
    asm("fma.rn.f32x2 %0, %1, %2, %3;" : "=l"(d) : "l"(a), "l"(b), "l"(c));
    return d;
}
__device__ __forceinline__ ull dup2(float x) {
    ull d; unsigned u = __float_as_uint(x);
    asm("mov.b64 %0, {%1, %1};" : "=l"(d) : "r"(u));
    return d;
}
__device__ __forceinline__ ull pack2(float a, float b) {
    ull d;
    asm("mov.b64 %0, {%1, %2};" : "=l"(d) : "r"(__float_as_uint(a)), "r"(__float_as_uint(b)));
    return d;
}
__device__ __forceinline__ float lo2(ull a) { return __uint_as_float((unsigned)a); }
__device__ __forceinline__ float hi2(ull a) { return __uint_as_float((unsigned)(a >> 32)); }

// ---------------- accurate sin/cos, immune to --use_fast_math ----------------
__device__ __forceinline__ float sin_poly(float r) {
    float r2 = r * r;
    float p = -2.50521084e-8f;
    p = fmaf(p, r2,  2.75573192e-6f);
    p = fmaf(p, r2, -1.98412698e-4f);
    p = fmaf(p, r2,  8.33333333e-3f);
    p = fmaf(p, r2, -1.66666667e-1f);
    return fmaf(p * r2, r, r);
}
__device__ __forceinline__ float cos_poly(float r) {
    float r2 = r * r;
    float p =  2.08767570e-9f;
    p = fmaf(p, r2, -2.75573192e-7f);
    p = fmaf(p, r2,  2.48015873e-5f);
    p = fmaf(p, r2, -1.38888889e-3f);
    p = fmaf(p, r2,  4.16666667e-2f);
    p = fmaf(p, r2, -0.5f);
    return fmaf(p, r2, 1.0f);
}
__device__ __forceinline__ float reduce_pi(float x, int* par) {
    float n = rintf(x * 0.318309886183790672f);
    float r = fmaf(n, -3.140625f,             x);
    r       = fmaf(n, -9.670257568359375e-4f, r);
    r       = fmaf(n, -6.27832957e-7f,        r);
    *par = ((int)n) & 1;
    return r;
}
__device__ __forceinline__ float sin_acc1(float x) {
    int par; float r = reduce_pi(x, &par);
    float s = sin_poly(r);
    return par ? -s : s;
}
__device__ __forceinline__ void sincos_acc(float x, float* so, float* co) {
    int par; float r = reduce_pi(x, &par);
    float s = sin_poly(r), c = cos_poly(r);
    if (par) { s = -s; c = -c; }
    *so = s; *co = c;
}

// ---------------- 128-wide sine layer ----------------
// out[j][p] = sin(30*(sum_k in[k][p]*W[k][j] + b[j]))
// Weights read straight from global (L1-resident: 64KB working set, 16x intra-warp dedup).
// thread tile: 8 j x 8 p (4 f32x2 point-pairs). sInB pre-offset to feature row 0.
template <int K>
__device__ __forceinline__ void big_layer(const float* __restrict__ sInB, float* __restrict__ sOut,
                                          const float* __restrict__ Wg, const float* __restrict__ bg,
                                          int jg, int pg) {
    const float*  ip = sInB + (pg << 3);
    const float4* wp = (const float4*)Wg;   // row k: quads [k*32 + jg*2], [k*32 + jg*2 + 1]
    ull acc[32];
#pragma unroll
    for (int i = 0; i < 32; i++) acc[i] = 0ull;

#pragma unroll 4
    for (int k = 0; k < K; k++) {
        const float* a = ip + k * STR;
        ull ap[4];
        ap[0] = *(const ull*)(a);
        ap[1] = *(const ull*)(a + 2);
        ap[2] = *(const ull*)(a + 4);
        ap[3] = *(const ull*)(a + 6);
        float4 wA = __ldg(wp + k * 32 + (jg << 1));
        float4 wB = __ldg(wp + k * 32 + (jg << 1) + 1);
        ull wq[8];
        wq[0] = dup2(wA.x); wq[1] = dup2(wA.y); wq[2] = dup2(wA.z); wq[3] = dup2(wA.w);
        wq[4] = dup2(wB.x); wq[5] = dup2(wB.y); wq[6] = dup2(wB.z); wq[7] = dup2(wB.w);
#pragma unroll
        for (int jj = 0; jj < 8; jj++)
#pragma unroll
            for (int pp = 0; pp < 4; pp++)
                acc[jj * 4 + pp] = fma2(ap[pp], wq[jj], acc[jj * 4 + pp]);
    }
    __syncthreads();   // all reads of sIn done before anyone overwrites sOut (may alias sIn)

    const int j0 = jg << 3, p0 = pg << 3;
#pragma unroll
    for (int jj = 0; jj < 8; jj++) {
        float bj = __ldg(bg + j0 + jj);
        float* orow = sOut + (j0 + jj) * STR + p0;
#pragma unroll
        for (int pp = 0; pp < 4; pp++) {
            float v0 = sin_acc1(OMEGA * (lo2(acc[jj * 4 + pp]) + bj));
            float v1 = sin_acc1(OMEGA * (hi2(acc[jj * 4 + pp]) + bj));
            *(ull*)(orow + 2 * pp) = pack2(v0, v1);
        }
    }
    __syncthreads();   // epilogue done before next layer's mainloop overwrites inputs
}

// SMEM floats: sAct 128*STR | sE 78*STR   (~107 KB -> 2 CTAs/SM)
#define SMEM_WORDS ((128 + 78) * STR)

__global__ void __launch_bounds__(NT, 2)
siren_kernel(const float* __restrict__ pts,
             const float* __restrict__ W0, const float* __restrict__ b0,
             const float* __restrict__ W1, const float* __restrict__ b1,
             const float* __restrict__ W2, const float* __restrict__ b2,
             const float* __restrict__ W3, const float* __restrict__ b3,
             const float* __restrict__ W4, const float* __restrict__ b4,
             const float* __restrict__ W5, const float* __restrict__ b5,
             const float* __restrict__ W6, const float* __restrict__ b6,
             const float* __restrict__ W7, const float* __restrict__ b7,
             float* __restrict__ out, int n) {
    extern __shared__ float sm[];
    float* sAct = sm;                    // [128][STR]
    float* sE   = sAct + 128 * STR;      // [78][STR]: rows 0..14 scalar, 15..17 x, 18..77 trig enc

    const int tid = threadIdx.x;
    const int pbase = blockIdx.x * BP;
    const int jg = tid & 15, pg = tid >> 4;

    // ---------------- positional encoding ----------------
    for (int idx = tid; idx < BP * 3; idx += NT) {
        int p = idx / 3, c = idx - 3 * p;
        sE[(15 + c) * STR + p] = pts[pbase * 3 + idx];
    }
    __syncthreads();
    for (int t = tid; t < BP * 30; t += NT) {
        int p = t & (BP - 1);
        int i = t >> 7;                 // 0..29
        int f = i / 3, c = i - 3 * f;
        float freq = 3.14159265358979323846f * (float)(1 << f);
        float ang = sE[(15 + c) * STR + p] * freq;
        float s, co; sincos_acc(ang, &s, &co);
        sE[(18 + 6 * f + c) * STR + p] = s;
        sE[(21 + 6 * f + c) * STR + p] = co;
    }
    __syncthreads();

    // ---------------- L0: enc(63) -> 128 ----------------
    big_layer<63>(sE + 15 * STR, sAct, W0, b0, jg, pg);
    // ---------------- L1..L3: 128 -> 128 ----------------
    big_layer<128>(sAct, sAct, W1, b1, jg, pg);
    big_layer<128>(sAct, sAct, W2, b2, jg, pg);
    big_layer<128>(sAct, sAct, W3, b3, jg, pg);

    // ---------------- L4: 128 -> 16, no activation; row0 -> density, rows1..15 -> scalar ----------------
    {
        const int j = tid & 15, pq = tid >> 4;
        const float* ip = sAct + (pq << 3);
        ull a4[4] = {0ull, 0ull, 0ull, 0ull};
#pragma unroll 4
        for (int k = 0; k < 128; k++) {
            const float* a = ip + k * STR;
            ull x0 = *(const ull*)(a);
            ull x1 = *(const ull*)(a + 2);
            ull x2 = *(const ull*)(a + 4);
            ull x3 = *(const ull*)(a + 6);
            ull w = dup2(__ldg(W4 + (k << 4) + j));
            a4[0] = fma2(x0, w, a4[0]);
            a4[1] = fma2(x1, w, a4[1]);
            a4[2] = fma2(x2, w, a4[2]);
            a4[3] = fma2(x3, w, a4[3]);
        }
        float bj = __ldg(b4 + j);
        if (j == 0) {
            float* od = out + n + pbase + (pq << 3);   // density block
#pragma unroll
            for (int q = 0; q < 4; q++) {
                od[2 * q]     = fmaxf(lo2(a4[q]) + bj, 0.0f);
                od[2 * q + 1] = fmaxf(hi2(a4[q]) + bj, 0.0f);
            }
        } else {
            float* orow = sE + (j - 1) * STR + (pq << 3);   // scalar features, rows 0..14
#pragma unroll
            for (int q = 0; q < 4; q++)
                *(ull*)(orow + 2 * q) = pack2(lo2(a4[q]) + bj, hi2(a4[q]) + bj);
        }
        __syncthreads();
    }

    // ---------------- L5: [scalar(15) | enc(63)] = 78 -> 128 ----------------
    big_layer<78>(sE, sAct, W5, b5, jg, pg);
    // ---------------- L6: 128 -> 128 ----------------
    big_layer<128>(sAct, sAct, W6, b6, jg, pg);

    // ---------------- L7: 128 -> 1 ----------------
    if (tid < BP) {
        float acc = 0.0f;
#pragma unroll 8
        for (int k = 0; k < 128; k++)
            acc = fmaf(sAct[k * STR + tid], __ldg(W7 + k), acc);
        out[pbase + tid] = acc + __ldg(b7);
    }
}

extern "C" void kernel_launch(void* const* d_in, const int* in_sizes, int n_in,
                              void* d_out, int out_size) {
    (void)n_in; (void)out_size;
    const float* pts = (const float*)d_in[0];
    const float* W0 = (const float*)d_in[1];  const float* b0 = (const float*)d_in[2];
    const float* W1 = (const float*)d_in[3];  const float* b1 = (const float*)d_in[4];
    const float* W2 = (const float*)d_in[5];  const float* b2 = (const float*)d_in[6];
    const float* W3 = (const float*)d_in[7];  const float* b3 = (const float*)d_in[8];
    const float* W4 = (const float*)d_in[9];  const float* b4 = (const float*)d_in[10];
    const float* W5 = (const float*)d_in[11]; const float* b5 = (const float*)d_in[12];
    const float* W6 = (const float*)d_in[13]; const float* b6 = (const float*)d_in[14];
    const float* W7 = (const float*)d_in[15]; const float* b7 = (const float*)d_in[16];
    float* out = (float*)d_out;

    int n = in_sizes[0] / 3;
    int blocks = n / BP;
    size_t shmem = (size_t)SMEM_WORDS * sizeof(float);   // ~107 KB -> 2 CTAs/SM

    cudaFuncSetAttribute(siren_kernel, cudaFuncAttributeMaxDynamicSharedMemorySize, (int)shmem);
    siren_kernel<<<blocks, NT, shmem>>>(pts, W0, b0, W1, b1, W2, b2, W3, b3,
                                        W4, b4, W5, b5, W6, b6, W7, b7, out, n);
}